// round 2
// baseline (speedup 1.0000x reference)
#include <cuda_runtime.h>
#include <cstdint>

using ull = unsigned long long;

__device__ __forceinline__ ull pack2(float x) {
    ull r; asm("mov.b64 %0,{%1,%1};" : "=l"(r) : "f"(x)); return r;
}
__device__ __forceinline__ float2 unpack2(ull v) {
    float2 f; asm("mov.b64 {%0,%1},%2;" : "=f"(f.x), "=f"(f.y) : "l"(v)); return f;
}
__device__ __forceinline__ void fma2(ull& d, ull a, ull b) {
    asm("fma.rn.f32x2 %0,%1,%2,%0;" : "+l"(d) : "l"(a), "l"(b));
}

// Ping-pong activation buffers (128 MB each). Allocations are forbidden;
// __device__ globals are the sanctioned scratch mechanism.
__device__ float g_bufA[33554432];
__device__ float g_bufB[33554432];

// ---------------------------------------------------------------------------
// First conv: non-overlapping 4x4 patches -> 64 ch + ReLU.
// in (128,256,256,1), filter (4,4,1,64) -> L0 [b][x][y][c] = (128,64,64,64)
// ---------------------------------------------------------------------------
__global__ void __launch_bounds__(256) first_conv(
    const float* __restrict__ in, const float* __restrict__ fw,
    const float* __restrict__ bias, float* __restrict__ out) {
    __shared__ float sIn[16 * 17];
    __shared__ float sW[1024];
    __shared__ float sB[64];
    const int tid = threadIdx.x;
    for (int j = tid; j < 1024; j += 256) sW[j] = fw[j];
    if (tid < 64) sB[tid] = bias[tid];
    const int P0 = blockIdx.x * 16;
    if (tid < 64) {
        const int pix = tid >> 2, p = tid & 3;
        const int P = P0 + pix, b = P >> 12, x = (P >> 6) & 63, y = P & 63;
        float4 v = *reinterpret_cast<const float4*>(
            in + ((size_t)(b * 256 + 4 * x + p)) * 256 + 4 * y);
        sIn[pix * 17 + p * 4 + 0] = v.x;
        sIn[pix * 17 + p * 4 + 1] = v.y;
        sIn[pix * 17 + p * 4 + 2] = v.z;
        sIn[pix * 17 + p * 4 + 3] = v.w;
    }
    __syncthreads();
    const int c = tid & 63, pq = tid >> 6;
    float acc[4] = {sB[c], sB[c], sB[c], sB[c]};
#pragma unroll
    for (int i = 0; i < 16; i++) {
        const float w = sW[i * 64 + c];
#pragma unroll
        for (int j = 0; j < 4; j++) acc[j] += sIn[(pq * 4 + j) * 17 + i] * w;
    }
#pragma unroll
    for (int j = 0; j < 4; j++)
        out[(size_t)(P0 + pq * 4 + j) * 64 + c] = fmaxf(acc[j], 0.0f);
}

// ---------------------------------------------------------------------------
// Node conv (levels 1..6).
// in  [NP,NP,B,2H,2H,64] -> out [NU,NU,B,H,H,64]
// fw  [NU,NU,2,2,64,64]  bias [NU,NU,64]
// Per node: M = B*H*H, K = 256 (k = (x*2+y)*64 + c), N = 64.
// K processed in 8 stages of 32 (half a quadrant's channels each).
// Microtile 4m x 8n per thread; packed f32x2 accumulators (FFMA2).
// ---------------------------------------------------------------------------
template <int NU, int NP, int HO>
__global__ void __launch_bounds__(256, 2) node_conv(
    const float* __restrict__ in, const float* __restrict__ fw,
    const float* __restrict__ bias, float* __restrict__ out) {
    constexpr int Bn = 128, C = 64, HI = 2 * HO, WI = 2 * HO, WO = HO;
    constexpr int M = Bn * HO * WO;
    __shared__ float sA[128 * 36];  // [m][k_local], pad 36
    __shared__ float sW[32 * 64];   // [k_local][o]

    const int tid = threadIdx.x;
    const int node = blockIdx.y;
    const int u = node / NU, v = node % NU;
    const int pu = (NP < NU) ? (u >> 1) : u;
    const int pv = (NP < NU) ? (v >> 1) : v;
    const float* inN = in + (size_t)(pu * NP + pv) * Bn * HI * WI * C;
    const float* fN = fw + (size_t)node * 4 * C * C;
    const float* bN = bias + (size_t)node * C;
    const int m0 = blockIdx.x * 128;

    const int c0 = (tid & 7) * 4;  // channel offset within stage (0..28)
    const int miB = tid >> 3;      // base m-row (0..31); rows miB + 32j
    const float* aptr[4];
#pragma unroll
    for (int j = 0; j < 4; j++) {
        const int m = m0 + miB + j * 32;
        const int b = m / (HO * WO);
        const int hw = m - b * HO * WO;
        const int h = hw / WO, w = hw - h * WO;
        aptr[j] = inN + (((size_t)b * HI + 2 * h) * WI + 2 * w) * C + c0;
    }

    float4 aR[4], wR[2];
    auto LDG = [&](int s) {
        const int x = s >> 2, y = (s >> 1) & 1, cb = (s & 1) * 32;
        const size_t off = (size_t)(x * WI + y) * C + cb;
#pragma unroll
        for (int j = 0; j < 4; j++)
            aR[j] = *reinterpret_cast<const float4*>(aptr[j] + off);
#pragma unroll
        for (int j = 0; j < 2; j++)
            wR[j] = *reinterpret_cast<const float4*>(fN + s * 2048 + (tid + j * 256) * 4);
    };
    auto STS = [&]() {
#pragma unroll
        for (int j = 0; j < 4; j++)
            *reinterpret_cast<float4*>(sA + (miB + j * 32) * 36 + c0) = aR[j];
#pragma unroll
        for (int j = 0; j < 2; j++)
            reinterpret_cast<float4*>(sW)[tid + j * 256] = wR[j];
    };

    ull acc[4][4];
#pragma unroll
    for (int i = 0; i < 4; i++)
#pragma unroll
        for (int p = 0; p < 4; p++) acc[i][p] = 0ull;

    const int pg = tid >> 3;  // 4 m-rows pg*4..pg*4+3
    const int cg = tid & 7;   // 8 outputs cg*8..cg*8+7

    LDG(0);
    STS();
    __syncthreads();

#pragma unroll 1
    for (int s = 0; s < 8; s++) {
        if (s < 7) LDG(s + 1);
#pragma unroll
        for (int k4 = 0; k4 < 32; k4 += 4) {
            float4 a4[4];
#pragma unroll
            for (int i = 0; i < 4; i++)
                a4[i] = *reinterpret_cast<const float4*>(sA + (pg * 4 + i) * 36 + k4);
#pragma unroll
            for (int kk = 0; kk < 4; kk++) {
                const ulonglong2 w01 =
                    *reinterpret_cast<const ulonglong2*>(sW + (k4 + kk) * 64 + cg * 8);
                const ulonglong2 w23 =
                    *reinterpret_cast<const ulonglong2*>(sW + (k4 + kk) * 64 + cg * 8 + 4);
                const ull a0 = pack2(reinterpret_cast<const float*>(&a4[0])[kk]);
                const ull a1 = pack2(reinterpret_cast<const float*>(&a4[1])[kk]);
                const ull a2 = pack2(reinterpret_cast<const float*>(&a4[2])[kk]);
                const ull a3 = pack2(reinterpret_cast<const float*>(&a4[3])[kk]);
                fma2(acc[0][0], a0, w01.x); fma2(acc[0][1], a0, w01.y);
                fma2(acc[0][2], a0, w23.x); fma2(acc[0][3], a0, w23.y);
                fma2(acc[1][0], a1, w01.x); fma2(acc[1][1], a1, w01.y);
                fma2(acc[1][2], a1, w23.x); fma2(acc[1][3], a1, w23.y);
                fma2(acc[2][0], a2, w01.x); fma2(acc[2][1], a2, w01.y);
                fma2(acc[2][2], a2, w23.x); fma2(acc[2][3], a2, w23.y);
                fma2(acc[3][0], a3, w01.x); fma2(acc[3][1], a3, w01.y);
                fma2(acc[3][2], a3, w23.x); fma2(acc[3][3], a3, w23.y);
            }
        }
        __syncthreads();
        if (s < 7) {
            STS();
            __syncthreads();
        }
    }

    const float4 b0 = *reinterpret_cast<const float4*>(bN + cg * 8);
    const float4 b1 = *reinterpret_cast<const float4*>(bN + cg * 8 + 4);
#pragma unroll
    for (int i = 0; i < 4; i++) {
        const int m = m0 + pg * 4 + i;
        float* op = out + ((size_t)node * M + m) * C + cg * 8;
        const float2 p0 = unpack2(acc[i][0]), p1 = unpack2(acc[i][1]);
        const float2 p2 = unpack2(acc[i][2]), p3 = unpack2(acc[i][3]);
        float4 r0 = make_float4(fmaxf(p0.x + b0.x, 0.f), fmaxf(p0.y + b0.y, 0.f),
                                fmaxf(p1.x + b0.z, 0.f), fmaxf(p1.y + b0.w, 0.f));
        float4 r1 = make_float4(fmaxf(p2.x + b1.x, 0.f), fmaxf(p2.y + b1.y, 0.f),
                                fmaxf(p3.x + b1.z, 0.f), fmaxf(p3.y + b1.w, 0.f));
        *reinterpret_cast<float4*>(op) = r0;
        *reinterpret_cast<float4*>(op + 4) = r1;
    }
}

// ---------------------------------------------------------------------------
// Decode: per node out[u,v,b,r,k] = sum_c feats[u,v,b,c]*Wd[u,v,r,c,k],
// scattered to (B, u*8+ou, v*8+ov, r) with k = ou*8+ov.
// ---------------------------------------------------------------------------
__global__ void __launch_bounds__(256) decode(
    const float* __restrict__ feats, const float* __restrict__ Wd,
    float* __restrict__ out) {
    extern __shared__ float dsm[];
    float* sF = dsm;          // 128 x 64
    float* sWd = dsm + 8192;  // 2 x 64 x 64
    const int tid = threadIdx.x;
    const int node = blockIdx.x, u = node >> 3, v = node & 7;
    const float* fN = feats + (size_t)node * 8192;
    const float* wN = Wd + (size_t)node * 8192;
#pragma unroll
    for (int j = 0; j < 8; j++) {
        const int f4 = tid + j * 256;
        reinterpret_cast<float4*>(sF)[f4] = reinterpret_cast<const float4*>(fN)[f4];
        reinterpret_cast<float4*>(sWd)[f4] = reinterpret_cast<const float4*>(wN)[f4];
    }
    __syncthreads();
    const int bg = tid >> 4, ng = tid & 15, r = ng >> 3, kk0 = (ng & 7) * 8;
    float acc[8][8];
#pragma unroll
    for (int i = 0; i < 8; i++)
#pragma unroll
        for (int j = 0; j < 8; j++) acc[i][j] = 0.0f;
#pragma unroll 4
    for (int k = 0; k < 64; k++) {
        const float4 w0 = *reinterpret_cast<const float4*>(sWd + r * 4096 + k * 64 + kk0);
        const float4 w1 = *reinterpret_cast<const float4*>(sWd + r * 4096 + k * 64 + kk0 + 4);
        const float wv[8] = {w0.x, w0.y, w0.z, w0.w, w1.x, w1.y, w1.z, w1.w};
#pragma unroll
        for (int i = 0; i < 8; i++) {
            const float a = sF[(bg * 8 + i) * 64 + k];
#pragma unroll
            for (int j = 0; j < 8; j++) acc[i][j] += a * wv[j];
        }
    }
    const int ou = ng & 7;
#pragma unroll
    for (int i = 0; i < 8; i++) {
        const int b = bg * 8 + i;
#pragma unroll
        for (int j = 0; j < 8; j++)
            out[(((size_t)b * 64 + u * 8 + ou) * 64 + (v * 8 + j)) * 2 + r] = acc[i][j];
    }
}

// ---------------------------------------------------------------------------
extern "C" void kernel_launch(void* const* d_in, const int* in_sizes, int n_in,
                              void* d_out, int out_size) {
    const float* in_data = (const float*)d_in[0];
    const float* in_filter = (const float*)d_in[1];
    const float* in_bias = (const float*)d_in[2];
    const float* f[6];
    const float* bb[6];
    for (int l = 0; l < 6; l++) {
        f[l] = (const float*)d_in[3 + 2 * l];
        bb[l] = (const float*)d_in[4 + 2 * l];
    }
    const float* Wd = (const float*)d_in[15];
    float* out = (float*)d_out;

    float *A, *B;
    cudaGetSymbolAddress((void**)&A, g_bufA);
    cudaGetSymbolAddress((void**)&B, g_bufB);
    cudaFuncSetAttribute(decode, cudaFuncAttributeMaxDynamicSharedMemorySize, 65536);

    first_conv<<<32768, 256>>>(in_data, in_filter, in_bias, A);
    node_conv<2, 1, 32><<<dim3(1024, 4), 256>>>(A, f[0], bb[0], B);
    node_conv<4, 2, 16><<<dim3(256, 16), 256>>>(B, f[1], bb[1], A);
    node_conv<8, 4, 8><<<dim3(64, 64), 256>>>(A, f[2], bb[2], B);
    node_conv<8, 8, 4><<<dim3(16, 64), 256>>>(B, f[3], bb[3], A);
    node_conv<8, 8, 2><<<dim3(4, 64), 256>>>(A, f[4], bb[4], B);
    node_conv<8, 8, 1><<<dim3(1, 64), 256>>>(B, f[5], bb[5], A);
    decode<<<64, 256, 65536>>>(A, Wd, out);
}

// round 3
// speedup vs baseline: 1.2779x; 1.2779x over previous
#include <cuda_runtime.h>
#include <cstdint>

using ull = unsigned long long;

__device__ __forceinline__ ull pack2(float x) {
    ull r; asm("mov.b64 %0,{%1,%1};" : "=l"(r) : "f"(x)); return r;
}
__device__ __forceinline__ float2 unpack2(ull v) {
    float2 f; asm("mov.b64 {%0,%1},%2;" : "=f"(f.x), "=f"(f.y) : "l"(v)); return f;
}
__device__ __forceinline__ void fma2(ull& d, ull a, ull b) {
    asm("fma.rn.f32x2 %0,%1,%2,%0;" : "+l"(d) : "l"(a), "l"(b));
}

// Ping-pong activation buffers. Allocations are forbidden; __device__ globals
// are the sanctioned scratch mechanism.
__device__ float g_bufA[33554432];
__device__ float g_bufB[33554432];

// ---------------------------------------------------------------------------
// First conv: non-overlapping 4x4 patches -> 64 ch + ReLU.
// in (128,256,256,1), filter (4,4,1,64) -> L0 [b][x][y][c] = (128,64,64,64)
// ---------------------------------------------------------------------------
__global__ void __launch_bounds__(256) first_conv(
    const float* __restrict__ in, const float* __restrict__ fw,
    const float* __restrict__ bias, float* __restrict__ out) {
    __shared__ float sIn[16 * 17];
    __shared__ float sW[1024];
    __shared__ float sB[64];
    const int tid = threadIdx.x;
    for (int j = tid; j < 1024; j += 256) sW[j] = fw[j];
    if (tid < 64) sB[tid] = bias[tid];
    const int P0 = blockIdx.x * 16;
    if (tid < 64) {
        const int pix = tid >> 2, p = tid & 3;
        const int P = P0 + pix, b = P >> 12, x = (P >> 6) & 63, y = P & 63;
        float4 v = *reinterpret_cast<const float4*>(
            in + ((size_t)(b * 256 + 4 * x + p)) * 256 + 4 * y);
        sIn[pix * 17 + p * 4 + 0] = v.x;
        sIn[pix * 17 + p * 4 + 1] = v.y;
        sIn[pix * 17 + p * 4 + 2] = v.z;
        sIn[pix * 17 + p * 4 + 3] = v.w;
    }
    __syncthreads();
    const int c = tid & 63, pq = tid >> 6;
    float acc[4] = {sB[c], sB[c], sB[c], sB[c]};
#pragma unroll
    for (int i = 0; i < 16; i++) {
        const float w = sW[i * 64 + c];
#pragma unroll
        for (int j = 0; j < 4; j++) acc[j] += sIn[(pq * 4 + j) * 17 + i] * w;
    }
#pragma unroll
    for (int j = 0; j < 4; j++)
        out[(size_t)(P0 + pq * 4 + j) * 64 + c] = fmaxf(acc[j], 0.0f);
}

// ---------------------------------------------------------------------------
// Node conv (levels 1..6).
// in  [NP,NP,B,2H,2H,64] -> out [NU,NU,B,H,H,64]
// fw  [NU,NU,2,2,64,64]  bias [NU,NU,64]
// Per node: M = B*H*H, K = 256 (k = (x*2+y)*64 + c), N = 64.
// K in 8 stages of 32. Microtile 8m x 8n per thread, FFMA2 accumulators.
// W stored split-half: sW[h][k][cg*4] so each quarter-warp W read is 128
// contiguous bytes (conflict-free).
// ---------------------------------------------------------------------------
template <int NU, int NP, int HO, int NT>
__global__ void __launch_bounds__(NT, 1) node_conv(
    const float* __restrict__ in, const float* __restrict__ fw,
    const float* __restrict__ bias, float* __restrict__ out) {
    constexpr int Bn = 128, C = 64, HI = 2 * HO, WI = 2 * HO, WO = HO;
    constexpr int M = Bn * HO * WO;
    constexpr int MT = NT;        // block m-tile
    constexpr int RSTRIDE = 36;   // padded k-row for sA
    __shared__ float sA[MT * RSTRIDE];  // [m][k_local]
    __shared__ float sW[2 * 32 * 32];   // [h][k][cg*4+j]

    const int tid = threadIdx.x;
    const int node = blockIdx.y;
    const int u = node / NU, v = node % NU;
    const int pu = (NP < NU) ? (u >> 1) : u;
    const int pv = (NP < NU) ? (v >> 1) : v;
    const float* inN = in + (size_t)(pu * NP + pv) * Bn * HI * WI * C;
    const float* fN = fw + (size_t)node * 4 * C * C;
    const float* bN = bias + (size_t)node * C;
    const int m0 = blockIdx.x * MT;

    const int c0 = (tid & 7) * 4;  // channel offset within stage
    const int miB = tid >> 3;      // base m-row; rows miB + (MT/8)*j
    const float* aptr[8];
#pragma unroll
    for (int j = 0; j < 8; j++) {
        const int m = m0 + miB + j * (MT / 8);
        const int b = m / (HO * WO);
        const int hw = m - b * HO * WO;
        const int h = hw / WO, w = hw - h * WO;
        aptr[j] = inN + (((size_t)b * HI + 2 * h) * WI + 2 * w) * C + c0;
    }

    constexpr int WJ = 512 / NT;  // W float4s per thread per stage
    float4 aR[8], wR[WJ];
    auto LDG = [&](int s) {
        const int x = s >> 2, y = (s >> 1) & 1, cb = (s & 1) * 32;
        const size_t off = (size_t)(x * WI + y) * C + cb;
#pragma unroll
        for (int j = 0; j < 8; j++)
            aR[j] = *reinterpret_cast<const float4*>(aptr[j] + off);
#pragma unroll
        for (int j = 0; j < WJ; j++)
            wR[j] = *reinterpret_cast<const float4*>(fN + s * 2048 + (tid + j * NT) * 4);
    };
    auto STS = [&]() {
#pragma unroll
        for (int j = 0; j < 8; j++)
            *reinterpret_cast<float4*>(sA + (miB + j * (MT / 8)) * RSTRIDE + c0) = aR[j];
#pragma unroll
        for (int j = 0; j < WJ; j++) {
            const int f4 = tid + j * NT;
            const int k = f4 >> 4;
            const int n0 = (f4 & 15) * 4;
            const int h = (n0 >> 2) & 1;
            const int pos = (n0 >> 3) * 4;
            *reinterpret_cast<float4*>(sW + h * 1024 + k * 32 + pos) = wR[j];
        }
    };

    ull acc[8][4];
#pragma unroll
    for (int i = 0; i < 8; i++)
#pragma unroll
        for (int p = 0; p < 4; p++) acc[i][p] = 0ull;

    const int pg = tid >> 3;  // 8 m-rows pg*8..pg*8+7
    const int cg = tid & 7;   // 8 outputs cg*8..cg*8+7

    LDG(0);
    STS();
    __syncthreads();

#pragma unroll 1
    for (int s = 0; s < 8; s++) {
        if (s < 7) LDG(s + 1);
#pragma unroll
        for (int k4 = 0; k4 < 32; k4 += 4) {
            float4 a4[8];
#pragma unroll
            for (int i = 0; i < 8; i++)
                a4[i] = *reinterpret_cast<const float4*>(sA + (pg * 8 + i) * RSTRIDE + k4);
#pragma unroll
            for (int kk = 0; kk < 4; kk++) {
                const ulonglong2 w01 =
                    *reinterpret_cast<const ulonglong2*>(sW + (k4 + kk) * 32 + cg * 4);
                const ulonglong2 w23 =
                    *reinterpret_cast<const ulonglong2*>(sW + 1024 + (k4 + kk) * 32 + cg * 4);
#pragma unroll
                for (int i = 0; i < 8; i++) {
                    const ull a = pack2(reinterpret_cast<const float*>(&a4[i])[kk]);
                    fma2(acc[i][0], a, w01.x);
                    fma2(acc[i][1], a, w01.y);
                    fma2(acc[i][2], a, w23.x);
                    fma2(acc[i][3], a, w23.y);
                }
            }
        }
        __syncthreads();
        if (s < 7) {
            STS();
            __syncthreads();
        }
    }

    const float4 b0 = *reinterpret_cast<const float4*>(bN + cg * 8);
    const float4 b1 = *reinterpret_cast<const float4*>(bN + cg * 8 + 4);
#pragma unroll
    for (int i = 0; i < 8; i++) {
        const int m = m0 + pg * 8 + i;
        float* op = out + ((size_t)node * M + m) * C + cg * 8;
        const float2 p0 = unpack2(acc[i][0]), p1 = unpack2(acc[i][1]);
        const float2 p2 = unpack2(acc[i][2]), p3 = unpack2(acc[i][3]);
        float4 r0 = make_float4(fmaxf(p0.x + b0.x, 0.f), fmaxf(p0.y + b0.y, 0.f),
                                fmaxf(p1.x + b0.z, 0.f), fmaxf(p1.y + b0.w, 0.f));
        float4 r1 = make_float4(fmaxf(p2.x + b1.x, 0.f), fmaxf(p2.y + b1.y, 0.f),
                                fmaxf(p3.x + b1.z, 0.f), fmaxf(p3.y + b1.w, 0.f));
        *reinterpret_cast<float4*>(op) = r0;
        *reinterpret_cast<float4*>(op + 4) = r1;
    }
}

// ---------------------------------------------------------------------------
// Decode: per node out[u,v,b,r,k] = sum_c feats[u,v,b,c]*Wd[u,v,r,c,k],
// scattered to (B, u*8+ou, v*8+ov, r) with k = ou*8+ov.
// ---------------------------------------------------------------------------
__global__ void __launch_bounds__(256) decode(
    const float* __restrict__ feats, const float* __restrict__ Wd,
    float* __restrict__ out) {
    extern __shared__ float dsm[];
    float* sF = dsm;          // 128 x 64
    float* sWd = dsm + 8192;  // 2 x 64 x 64
    const int tid = threadIdx.x;
    const int node = blockIdx.x, u = node >> 3, v = node & 7;
    const float* fN = feats + (size_t)node * 8192;
    const float* wN = Wd + (size_t)node * 8192;
#pragma unroll
    for (int j = 0; j < 8; j++) {
        const int f4 = tid + j * 256;
        reinterpret_cast<float4*>(sF)[f4] = reinterpret_cast<const float4*>(fN)[f4];
        reinterpret_cast<float4*>(sWd)[f4] = reinterpret_cast<const float4*>(wN)[f4];
    }
    __syncthreads();
    const int bg = tid >> 4, ng = tid & 15, r = ng >> 3, kk0 = (ng & 7) * 8;
    float acc[8][8];
#pragma unroll
    for (int i = 0; i < 8; i++)
#pragma unroll
        for (int j = 0; j < 8; j++) acc[i][j] = 0.0f;
#pragma unroll 4
    for (int k = 0; k < 64; k++) {
        const float4 w0 = *reinterpret_cast<const float4*>(sWd + r * 4096 + k * 64 + kk0);
        const float4 w1 = *reinterpret_cast<const float4*>(sWd + r * 4096 + k * 64 + kk0 + 4);
        const float wv[8] = {w0.x, w0.y, w0.z, w0.w, w1.x, w1.y, w1.z, w1.w};
#pragma unroll
        for (int i = 0; i < 8; i++) {
            const float a = sF[(bg * 8 + i) * 64 + k];
#pragma unroll
            for (int j = 0; j < 8; j++) acc[i][j] += a * wv[j];
        }
    }
    const int ou = ng & 7;
#pragma unroll
    for (int i = 0; i < 8; i++) {
        const int b = bg * 8 + i;
#pragma unroll
        for (int j = 0; j < 8; j++)
            out[(((size_t)b * 64 + u * 8 + ou) * 64 + (v * 8 + j)) * 2 + r] = acc[i][j];
    }
}

// ---------------------------------------------------------------------------
extern "C" void kernel_launch(void* const* d_in, const int* in_sizes, int n_in,
                              void* d_out, int out_size) {
    const float* in_data = (const float*)d_in[0];
    const float* in_filter = (const float*)d_in[1];
    const float* in_bias = (const float*)d_in[2];
    const float* f[6];
    const float* bb[6];
    for (int l = 0; l < 6; l++) {
        f[l] = (const float*)d_in[3 + 2 * l];
        bb[l] = (const float*)d_in[4 + 2 * l];
    }
    const float* Wd = (const float*)d_in[15];
    float* out = (float*)d_out;

    float *A, *B;
    cudaGetSymbolAddress((void**)&A, g_bufA);
    cudaGetSymbolAddress((void**)&B, g_bufB);
    cudaFuncSetAttribute(decode, cudaFuncAttributeMaxDynamicSharedMemorySize, 65536);

    first_conv<<<32768, 256>>>(in_data, in_filter, in_bias, A);
    node_conv<2, 1, 32, 256><<<dim3(512, 4), 256>>>(A, f[0], bb[0], B);
    node_conv<4, 2, 16, 256><<<dim3(128, 16), 256>>>(B, f[1], bb[1], A);
    node_conv<8, 4, 8, 256><<<dim3(32, 64), 256>>>(A, f[2], bb[2], B);
    node_conv<8, 8, 4, 256><<<dim3(8, 64), 256>>>(B, f[3], bb[3], A);
    node_conv<8, 8, 2, 256><<<dim3(2, 64), 256>>>(A, f[4], bb[4], B);
    node_conv<8, 8, 1, 128><<<dim3(1, 64), 128>>>(B, f[5], bb[5], A);
    decode<<<64, 256, 65536>>>(A, Wd, out);
}